// round 2
// baseline (speedup 1.0000x reference)
#include <cuda_runtime.h>
#include <math.h>

#define BB 256
#define LL 128
#define CC 256
#define HH 512
#define G4H 2048   // 4*HH

// ---------------- scratch (device globals: no allocation allowed) ----------------
__device__ float g_preM[(size_t)BB * LL * HH];    // 32768 x 512   (X@Wmx + bmx + bmh)
__device__ float g_preG2[(size_t)BB * LL * G4H];  // 32768 x 2048  (gates precompute)
__device__ float g_W2[HH * G4H];                  // Wmh @ Whm
__device__ float g_W2i[HH * G4H];                 // interleaved: [k][h*4+g]
__device__ float g_h[2][BB * HH];                 // ping-pong hidden state
__device__ float g_Cst[BB * HH];                  // cell state

// ---------------- packed f32x2 helpers (2x fp32 FMA throughput on sm_103a) -------
__device__ __forceinline__ unsigned long long pk2(float x, float y) {
    unsigned long long r;
    asm("mov.b64 %0, {%1, %2};" : "=l"(r) : "f"(x), "f"(y));
    return r;
}
__device__ __forceinline__ void upk2(unsigned long long v, float& x, float& y) {
    asm("mov.b64 {%0, %1}, %2;" : "=f"(x), "=f"(y) : "l"(v));
}
__device__ __forceinline__ void fma2(unsigned long long& d, unsigned long long a, unsigned long long b) {
    asm("fma.rn.f32x2 %0, %1, %2, %0;" : "+l"(d) : "l"(a), "l"(b));
}
__device__ __forceinline__ float sigm(float v) { return 1.f / (1.f + expf(-v)); }

// ---------------- zero init ----------------
__global__ void zero2_kernel(int n) {
    int i = blockIdx.x * blockDim.x + threadIdx.x;
    if (i < n) { g_h[0][i] = 0.f; g_Cst[i] = 0.f; }
}

// ---------------- attention: x_score -> softmax -> x_tilde (time-invariant!) -----
__global__ void attn_xtilde(const float* __restrict__ x, const float* __restrict__ Wa,
                            const float* __restrict__ ba, float* __restrict__ out_xt) {
    int b = blockIdx.x;
    int c = threadIdx.x;  // 256 threads, one per channel
    __shared__ float wx[LL];
    __shared__ float red[CC];
    if (c < LL) wx[c] = Wa[2 * HH + c];
    __syncthreads();

    const float* xb = x + (size_t)b * LL * CC;
    float s = 0.f;
#pragma unroll 4
    for (int l = 0; l < LL; l++) s += xb[l * CC + c] * wx[l];
    s += ba[0];

    red[c] = s; __syncthreads();
#pragma unroll
    for (int st = 128; st > 0; st >>= 1) {
        if (c < st) red[c] = fmaxf(red[c], red[c + st]);
        __syncthreads();
    }
    float m = red[0];
    __syncthreads();
    float e = expf(s - m);
    red[c] = e; __syncthreads();
#pragma unroll
    for (int st = 128; st > 0; st >>= 1) {
        if (c < st) red[c] += red[c + st];
        __syncthreads();
    }
    float alpha = e / red[0];

    float* ob = out_xt + (size_t)b * LL * CC;
#pragma unroll 4
    for (int l = 0; l < LL; l++) ob[l * CC + c] = alpha * xb[l * CC + c];
}

// ---------------- fp32 SGEMM, 128x128x16 tile, 8x8 microtile, f32x2 FMAs ---------
#define BM 128
#define BN 128
#define BK 16

__global__ __launch_bounds__(256, 2) void sgemm_f32(
    const float* __restrict__ A, const float* __restrict__ Bm, float* __restrict__ Cm,
    int M, int N, int K,
    const float* __restrict__ bias1, const float* __restrict__ bias2, int accum) {
    __shared__ alignas(16) float As[BK][BM + 4];
    __shared__ alignas(16) float Bs[BK][BN];

    int tid = threadIdx.x;
    int bm = blockIdx.y * BM;
    int bn = blockIdx.x * BN;
    int tx = tid & 15, ty = tid >> 4;
    int row = ty * 8, col = tx * 8;

    unsigned long long acc[8][4];
#pragma unroll
    for (int i = 0; i < 8; i++)
#pragma unroll
        for (int j = 0; j < 4; j++) acc[i][j] = 0ULL;

    for (int k0 = 0; k0 < K; k0 += BK) {
#pragma unroll
        for (int i = 0; i < 2; i++) {
            int idx = tid + i * 256;
            int r = idx >> 2;
            int q = (idx & 3) << 2;
            float4 v = *(const float4*)(A + (size_t)(bm + r) * K + k0 + q);
            As[q + 0][r] = v.x; As[q + 1][r] = v.y; As[q + 2][r] = v.z; As[q + 3][r] = v.w;
        }
#pragma unroll
        for (int i = 0; i < 2; i++) {
            int idx = tid + i * 256;
            int r = idx >> 5;
            int c = (idx & 31) << 2;
            *(float4*)&Bs[r][c] = *(const float4*)(Bm + (size_t)(k0 + r) * N + bn + c);
        }
        __syncthreads();
#pragma unroll
        for (int kk = 0; kk < BK; kk++) {
            float4 a0 = *(const float4*)&As[kk][row];
            float4 a1 = *(const float4*)&As[kk][row + 4];
            float4 b0 = *(const float4*)&Bs[kk][col];
            float4 b1 = *(const float4*)&Bs[kk][col + 4];
            unsigned long long bp0 = pk2(b0.x, b0.y), bp1 = pk2(b0.z, b0.w);
            unsigned long long bp2 = pk2(b1.x, b1.y), bp3 = pk2(b1.z, b1.w);
            float av[8] = {a0.x, a0.y, a0.z, a0.w, a1.x, a1.y, a1.z, a1.w};
#pragma unroll
            for (int i = 0; i < 8; i++) {
                unsigned long long ap = pk2(av[i], av[i]);
                fma2(acc[i][0], ap, bp0);
                fma2(acc[i][1], ap, bp1);
                fma2(acc[i][2], ap, bp2);
                fma2(acc[i][3], ap, bp3);
            }
        }
        __syncthreads();
    }

    float badd[8];
#pragma unroll
    for (int j = 0; j < 8; j++) {
        float v = 0.f;
        if (bias1) v += bias1[bn + col + j];
        if (bias2) v += bias2[bn + col + j];
        badd[j] = v;
    }
#pragma unroll
    for (int i = 0; i < 8; i++) {
        size_t off = (size_t)(bm + row + i) * N + bn + col;
        float o[8];
#pragma unroll
        for (int j = 0; j < 4; j++) upk2(acc[i][j], o[2 * j], o[2 * j + 1]);
#pragma unroll
        for (int j = 0; j < 8; j++) o[j] += badd[j];
        if (accum) {
            float4 c0 = *(const float4*)(Cm + off);
            float4 c1 = *(const float4*)(Cm + off + 4);
            o[0] += c0.x; o[1] += c0.y; o[2] += c0.z; o[3] += c0.w;
            o[4] += c1.x; o[5] += c1.y; o[6] += c1.z; o[7] += c1.w;
        }
        float4 r0 = make_float4(o[0], o[1], o[2], o[3]);
        float4 r1 = make_float4(o[4], o[5], o[6], o[7]);
        *(float4*)(Cm + off) = r0;
        *(float4*)(Cm + off + 4) = r1;
    }
}

// ---------------- interleave W2: [k][g*H+h] -> [k][h*4+g] -------------------------
__global__ void interleaveW2() {
    int i = blockIdx.x * blockDim.x + threadIdx.x;
    if (i < HH * G4H) {
        int k = i >> 11;          // /2048
        int r = i & 2047;
        int h = r >> 2;
        int g = r & 3;
        g_W2i[i] = g_W2[k * G4H + g * HH + h];
    }
}

// ---------------- fused recurrence step: gates = preG2[t] + h @ W2, + LSTM cell ---
// tile: 32 h  x 32 b, 4 gates per h. grid (16 htiles, 8 btiles) = 128 blocks.
__global__ __launch_bounds__(256) void lstm_step(
    float* __restrict__ out_h, float* __restrict__ out_c, int t) {
    __shared__ alignas(16) float Hs[32][33];    // [k][b]
    __shared__ alignas(16) float Ws[32][128];   // [k][h*4+g] (tile-local)

    const float* __restrict__ hprev = (t & 1) ? g_h[1] : g_h[0];
    float* __restrict__ hnext = (t & 1) ? g_h[0] : g_h[1];

    int tid = threadIdx.x;
    int hidx = tid & 31, brow = tid >> 5;
    int h0 = blockIdx.x * 32;
    int b0 = blockIdx.y * 32;

    unsigned long long acc[4][2];
#pragma unroll
    for (int i = 0; i < 4; i++) { acc[i][0] = 0ULL; acc[i][1] = 0ULL; }

    for (int k0 = 0; k0 < HH; k0 += 32) {
        {   // load h tile transposed: 256 threads x 1 float4 = 32x32
            int r = tid >> 3;
            int q = (tid & 7) << 2;
            float4 v = *(const float4*)(hprev + (size_t)(b0 + r) * HH + k0 + q);
            Hs[q + 0][r] = v.x; Hs[q + 1][r] = v.y; Hs[q + 2][r] = v.z; Hs[q + 3][r] = v.w;
        }
#pragma unroll
        for (int i = 0; i < 4; i++) {  // load W2i tile: 32k x 128 cols
            int idx = tid + i * 256;
            int r = idx >> 5;
            int c = (idx & 31) << 2;
            *(float4*)&Ws[r][c] = *(const float4*)(g_W2i + (size_t)(k0 + r) * G4H + h0 * 4 + c);
        }
        __syncthreads();
#pragma unroll
        for (int kk = 0; kk < 32; kk++) {
            float4 w = *(const float4*)&Ws[kk][hidx << 2];
            unsigned long long wlo = pk2(w.x, w.y), whi = pk2(w.z, w.w);
#pragma unroll
            for (int bi = 0; bi < 4; bi++) {
                float a = Hs[kk][brow + bi * 8];   // warp-broadcast
                unsigned long long ap = pk2(a, a);
                fma2(acc[bi][0], ap, wlo);
                fma2(acc[bi][1], ap, whi);
            }
        }
        __syncthreads();
    }

    int h = h0 + hidx;
#pragma unroll
    for (int bi = 0; bi < 4; bi++) {
        int b = b0 + brow + bi * 8;
        size_t gbase = ((size_t)b * LL + t) * G4H;
        float gi_, gf_, gg_, go_;
        upk2(acc[bi][0], gi_, gf_);
        upk2(acc[bi][1], gg_, go_);
        gi_ += g_preG2[gbase + 0 * HH + h];
        gf_ += g_preG2[gbase + 1 * HH + h];
        gg_ += g_preG2[gbase + 2 * HH + h];
        go_ += g_preG2[gbase + 3 * HH + h];

        size_t sh = (size_t)b * HH + h;
        float Cold = g_Cst[sh];
        float Cn = sigm(gf_) * Cold + sigm(gi_) * tanhf(gg_);
        float hn = sigm(go_) * tanhf(Cn);
        g_Cst[sh] = Cn;
        hnext[sh] = hn;
        size_t ob = ((size_t)b * LL + t) * HH + h;
        out_h[ob] = hn;
        out_c[ob] = Cn;
    }
}

// ---------------- launch ----------------
extern "C" void kernel_launch(void* const* d_in, const int* in_sizes, int n_in,
                              void* d_out, int out_size) {
    const float* x   = (const float*)d_in[0];
    const float* Wih = (const float*)d_in[1];
    const float* bih = (const float*)d_in[2];
    const float* Wmx = (const float*)d_in[3];
    const float* bmx = (const float*)d_in[4];
    const float* Wmh = (const float*)d_in[5];
    const float* bmh = (const float*)d_in[6];
    const float* Whm = (const float*)d_in[7];
    const float* bhm = (const float*)d_in[8];
    const float* Wa  = (const float*)d_in[9];
    const float* ba  = (const float*)d_in[10];

    float* out    = (float*)d_out;
    float* out_h  = out;
    float* out_c  = out + (size_t)BB * LL * HH;
    float* out_xt = out + (size_t)2 * BB * LL * HH;

    float *preM, *preG2, *W2;
    cudaGetSymbolAddress((void**)&preM, g_preM);
    cudaGetSymbolAddress((void**)&preG2, g_preG2);
    cudaGetSymbolAddress((void**)&W2, g_W2);

    // init state
    zero2_kernel<<<(BB * HH + 255) / 256, 256>>>(BB * HH);

    // attention path (time-invariant softmax) -> x_tilde output
    attn_xtilde<<<BB, 256>>>(x, Wa, ba, out_xt);

    // preM = X @ Wmx + (bmx + bmh)            [32768 x 512]
    sgemm_f32<<<dim3(HH / BN, (BB * LL) / BM), 256>>>(
        x, Wmx, preM, BB * LL, HH, CC, bmx, bmh, 0);
    // preG2 = X @ Wih + (bih + bhm)           [32768 x 2048]
    sgemm_f32<<<dim3(G4H / BN, (BB * LL) / BM), 256>>>(
        x, Wih, preG2, BB * LL, G4H, CC, bih, bhm, 0);
    // preG2 += preM @ Whm
    sgemm_f32<<<dim3(G4H / BN, (BB * LL) / BM), 256>>>(
        preM, Whm, preG2, BB * LL, G4H, HH, nullptr, nullptr, 1);
    // W2 = Wmh @ Whm                          [512 x 2048]
    sgemm_f32<<<dim3(G4H / BN, HH / BM), 256>>>(
        Wmh, Whm, W2, HH, G4H, HH, nullptr, nullptr, 0);
    // interleave W2 for fused step epilogue
    interleaveW2<<<(HH * G4H) / 256, 256>>>();

    // sequential recurrence: 128 fused GEMM+cell steps
    for (int t = 0; t < LL; t++) {
        lstm_step<<<dim3(HH / 32, BB / 32), 256>>>(out_h, out_c, t);
    }
}

// round 3
// speedup vs baseline: 1.9103x; 1.9103x over previous
#include <cuda_runtime.h>
#include <math.h>

#define BB 256
#define LL 128
#define CC 256
#define HH 512
#define G4H 2048   // 4*HH

// ---------------- scratch (device globals: no allocation allowed) ----------------
__device__ float g_preG2[(size_t)BB * LL * G4H];  // 32768 x 2048 gates precompute
__device__ float g_W2[HH * G4H];                  // Wmh @ Whm
__device__ float g_W2i[HH * G4H];                 // interleaved: [k][h*4+g]
__device__ float g_Wcomb[CC * G4H];               // Wih + Wmx@Whm
__device__ float g_biasc[G4H];                    // combined bias row
__device__ float g_h[2][HH * BB];                 // ping-pong hidden, TRANSPOSED [h][b]
__device__ volatile unsigned g_bar;               // grid barrier counter

typedef unsigned long long ull;

// ---------------- packed f32x2 helpers -------------------------------------------
__device__ __forceinline__ ull pk2(float x, float y) {
    ull r; asm("mov.b64 %0, {%1, %2};" : "=l"(r) : "f"(x), "f"(y)); return r;
}
__device__ __forceinline__ void upk2(ull v, float& x, float& y) {
    asm("mov.b64 {%0, %1}, %2;" : "=f"(x), "=f"(y) : "l"(v));
}
__device__ __forceinline__ void fma2(ull& d, ull a, ull b) {
    asm("fma.rn.f32x2 %0, %1, %2, %0;" : "+l"(d) : "l"(a), "l"(b));
}
__device__ __forceinline__ float tanha(float x) {
    float y; asm("tanh.approx.f32 %0, %1;" : "=f"(y) : "f"(x)); return y;
}
__device__ __forceinline__ float sigma(float x) {
    return fmaf(tanha(x * 0.5f), 0.5f, 0.5f);
}

// ---------------- init: zero h buffer 0 (transposed) + barrier -------------------
__global__ void zero_init(int n) {
    int i = blockIdx.x * blockDim.x + threadIdx.x;
    if (i < n) g_h[0][i] = 0.f;
    if (i == 0) g_bar = 0u;
}

// ---------------- attention: softmax is time-invariant ---------------------------
__global__ void attn_xtilde(const float* __restrict__ x, const float* __restrict__ Wa,
                            const float* __restrict__ ba, float* __restrict__ out_xt) {
    int b = blockIdx.x;
    int c = threadIdx.x;
    __shared__ float wx[LL];
    __shared__ float red[CC];
    if (c < LL) wx[c] = Wa[2 * HH + c];
    __syncthreads();

    const float* xb = x + (size_t)b * LL * CC;
    float s = 0.f;
#pragma unroll 4
    for (int l = 0; l < LL; l++) s += xb[l * CC + c] * wx[l];
    s += ba[0];

    red[c] = s; __syncthreads();
#pragma unroll
    for (int st = 128; st > 0; st >>= 1) {
        if (c < st) red[c] = fmaxf(red[c], red[c + st]);
        __syncthreads();
    }
    float m = red[0];
    __syncthreads();
    float e = expf(s - m);
    red[c] = e; __syncthreads();
#pragma unroll
    for (int st = 128; st > 0; st >>= 1) {
        if (c < st) red[c] += red[c + st];
        __syncthreads();
    }
    float alpha = e / red[0];

    float* ob = out_xt + (size_t)b * LL * CC;
#pragma unroll 4
    for (int l = 0; l < LL; l++) ob[l * CC + c] = alpha * xb[l * CC + c];
}

// ---------------- combined bias row: bih + bhm + (bmx+bmh)@Whm --------------------
__global__ void bias_comb(const float* __restrict__ bih, const float* __restrict__ bhm,
                          const float* __restrict__ bmx, const float* __restrict__ bmh,
                          const float* __restrict__ Whm) {
    __shared__ float bm[HH];
    int tid = threadIdx.x;
    for (int i = tid; i < HH; i += 256) bm[i] = bmx[i] + bmh[i];
    __syncthreads();
    int j = blockIdx.x * 256 + tid;
    float s = bih[j] + bhm[j];
#pragma unroll 8
    for (int k = 0; k < HH; k++) s += bm[k] * Whm[(size_t)k * G4H + j];
    g_biasc[j] = s;
}

// ---------------- fp32 SGEMM, 128x128x16 tile, 8x8 microtile, f32x2 FMAs ---------
#define BM 128
#define BN 128
#define BK 16

__global__ __launch_bounds__(256, 2) void sgemm_f32(
    const float* __restrict__ A, const float* __restrict__ Bm, float* __restrict__ Cm,
    int M, int N, int K,
    const float* __restrict__ bias1, const float* __restrict__ Cadd) {
    __shared__ alignas(16) float As[BK][BM + 4];
    __shared__ alignas(16) float Bs[BK][BN];

    int tid = threadIdx.x;
    int bm = blockIdx.y * BM;
    int bn = blockIdx.x * BN;
    int tx = tid & 15, ty = tid >> 4;
    int row = ty * 8, col = tx * 8;

    ull acc[8][4];
#pragma unroll
    for (int i = 0; i < 8; i++)
#pragma unroll
        for (int j = 0; j < 4; j++) acc[i][j] = 0ULL;

    for (int k0 = 0; k0 < K; k0 += BK) {
#pragma unroll
        for (int i = 0; i < 2; i++) {
            int idx = tid + i * 256;
            int r = idx >> 2;
            int q = (idx & 3) << 2;
            float4 v = *(const float4*)(A + (size_t)(bm + r) * K + k0 + q);
            As[q + 0][r] = v.x; As[q + 1][r] = v.y; As[q + 2][r] = v.z; As[q + 3][r] = v.w;
        }
#pragma unroll
        for (int i = 0; i < 2; i++) {
            int idx = tid + i * 256;
            int r = idx >> 5;
            int c = (idx & 31) << 2;
            *(float4*)&Bs[r][c] = *(const float4*)(Bm + (size_t)(k0 + r) * N + bn + c);
        }
        __syncthreads();
#pragma unroll
        for (int kk = 0; kk < BK; kk++) {
            float4 a0 = *(const float4*)&As[kk][row];
            float4 a1 = *(const float4*)&As[kk][row + 4];
            float4 b0 = *(const float4*)&Bs[kk][col];
            float4 b1 = *(const float4*)&Bs[kk][col + 4];
            ull bp0 = pk2(b0.x, b0.y), bp1 = pk2(b0.z, b0.w);
            ull bp2 = pk2(b1.x, b1.y), bp3 = pk2(b1.z, b1.w);
            float av[8] = {a0.x, a0.y, a0.z, a0.w, a1.x, a1.y, a1.z, a1.w};
#pragma unroll
            for (int i = 0; i < 8; i++) {
                ull ap = pk2(av[i], av[i]);
                fma2(acc[i][0], ap, bp0);
                fma2(acc[i][1], ap, bp1);
                fma2(acc[i][2], ap, bp2);
                fma2(acc[i][3], ap, bp3);
            }
        }
        __syncthreads();
    }

    float badd[8];
#pragma unroll
    for (int j = 0; j < 8; j++) badd[j] = bias1 ? bias1[bn + col + j] : 0.f;

#pragma unroll
    for (int i = 0; i < 8; i++) {
        size_t off = (size_t)(bm + row + i) * N + bn + col;
        float o[8];
#pragma unroll
        for (int j = 0; j < 4; j++) upk2(acc[i][j], o[2 * j], o[2 * j + 1]);
#pragma unroll
        for (int j = 0; j < 8; j++) o[j] += badd[j];
        if (Cadd) {
            float4 c0 = *(const float4*)(Cadd + off);
            float4 c1 = *(const float4*)(Cadd + off + 4);
            o[0] += c0.x; o[1] += c0.y; o[2] += c0.z; o[3] += c0.w;
            o[4] += c1.x; o[5] += c1.y; o[6] += c1.z; o[7] += c1.w;
        }
        *(float4*)(Cm + off) = make_float4(o[0], o[1], o[2], o[3]);
        *(float4*)(Cm + off + 4) = make_float4(o[4], o[5], o[6], o[7]);
    }
}

// ---------------- interleave W2: [k][g*H+h] -> [k][h*4+g] -------------------------
__global__ void interleaveW2() {
    int i = blockIdx.x * blockDim.x + threadIdx.x;
    if (i < HH * G4H) {
        int k = i >> 11;
        int r = i & 2047;
        int h = r >> 2;
        int g = r & 3;
        g_W2i[i] = g_W2[k * G4H + g * HH + h];
    }
}

// ---------------- persistent recurrence: all 128 steps in one kernel --------------
// grid (32 col-tiles, 4 b-tiles) = 128 CTAs x 256 threads; W2 slice in SMEM.
// col-tile = 64 interleaved gate cols = 16 h; b-tile = 64 batch rows.
// thread (tb=tid>>5, tc=tid&31): 8 b x 2 cols; f32x2 acc paired over b.
#define CHK 32
#define HSP 68   // Hs row pad (16B-aligned rows)

__global__ __launch_bounds__(256, 1) void lstm_persist(
    const float* __restrict__ preG2, float* __restrict__ out_h, float* __restrict__ out_c) {
    extern __shared__ float smem[];
    float* Ws = smem;                       // [512][64]
    float* Hs = smem + HH * 64;             // [2][CHK][HSP]

    const int tid = threadIdx.x;
    const int tc = tid & 31, tb = tid >> 5;
    const int ct = blockIdx.x;              // 0..31
    const int bt = blockIdx.y;              // 0..3
    const int b0 = bt * 64;
    const int col0 = ct * 64;
    const int parity = tc & 1;
    const int h = ct * 16 + (tc >> 1);
    const int bcell0 = b0 + tb * 8 + parity * 4;
    const int myc = tc * 2;
    const int kr0 = tid >> 4;               // 0..15
    const int c40 = (tid & 15) * 4;         // 0..60

    // load W2 slice once: 512 x 64 floats = 128KB
    for (int i = tid; i < HH * 16; i += 256) {
        int k = i >> 4;
        int c4 = (i & 15) * 4;
        *(float4*)&Ws[k * 64 + c4] = *(const float4*)&g_W2i[(size_t)k * G4H + col0 + c4];
    }
    __syncthreads();

    float Creg[4] = {0.f, 0.f, 0.f, 0.f};

    for (int t = 0; t < LL; t++) {
        const float* __restrict__ hprev = g_h[t & 1];
        float* __restrict__ hnext = g_h[(t + 1) & 1];

        // prefetch preG2 gate values for this t (16 scalars)
        float pg[4][4];
#pragma unroll
        for (int j = 0; j < 4; j++) {
            size_t rowb = ((size_t)(bcell0 + j) * LL + t) * G4H;
#pragma unroll
            for (int gg = 0; gg < 4; gg++) pg[j][gg] = preG2[rowb + gg * HH + h];
        }

        ull acc[4][2];
#pragma unroll
        for (int p = 0; p < 4; p++) { acc[p][0] = 0ULL; acc[p][1] = 0ULL; }

        if (t > 0) {
            // preload chunk 0 (h stored transposed [k][b], stride BB)
            float4 ld0 = __ldcg((const float4*)&hprev[(0 + kr0) * BB + b0 + c40]);
            float4 ld1 = __ldcg((const float4*)&hprev[(16 + kr0) * BB + b0 + c40]);

            for (int ch = 0; ch < 16; ch++) {
                float* HsB = Hs + (ch & 1) * (CHK * HSP);
                *(float4*)&HsB[kr0 * HSP + c40] = ld0;
                *(float4*)&HsB[(kr0 + 16) * HSP + c40] = ld1;
                __syncthreads();
                if (ch < 15) {
                    int k0n = (ch + 1) * CHK;
                    ld0 = __ldcg((const float4*)&hprev[(k0n + kr0) * BB + b0 + c40]);
                    ld1 = __ldcg((const float4*)&hprev[(k0n + 16 + kr0) * BB + b0 + c40]);
                }
                const float* W0 = Ws + ch * CHK * 64 + myc;
                const float* H0 = HsB + tb * 8;
#pragma unroll
                for (int kk = 0; kk < CHK; kk++) {
                    float4 hA = *(const float4*)(H0 + kk * HSP);
                    float4 hB = *(const float4*)(H0 + kk * HSP + 4);
                    float2 w = *(const float2*)(W0 + kk * 64);
                    ull w0 = pk2(w.x, w.x), w1 = pk2(w.y, w.y);
                    ull h01 = pk2(hA.x, hA.y), h23 = pk2(hA.z, hA.w);
                    ull h45 = pk2(hB.x, hB.y), h67 = pk2(hB.z, hB.w);
                    fma2(acc[0][0], h01, w0); fma2(acc[0][1], h01, w1);
                    fma2(acc[1][0], h23, w0); fma2(acc[1][1], h23, w1);
                    fma2(acc[2][0], h45, w0); fma2(acc[2][1], h45, w1);
                    fma2(acc[3][0], h67, w0); fma2(acc[3][1], h67, w1);
                }
            }
        }

        // --- exchange gate pairs between adjacent lanes (even: i,f  odd: g,o) ---
        ull s0, s1, s2, s3;
        if (!parity) { s0 = acc[2][0]; s1 = acc[3][0]; s2 = acc[2][1]; s3 = acc[3][1]; }
        else         { s0 = acc[0][0]; s1 = acc[1][0]; s2 = acc[0][1]; s3 = acc[1][1]; }
        ull r0 = __shfl_xor_sync(0xffffffffu, s0, 1);
        ull r1 = __shfl_xor_sync(0xffffffffu, s1, 1);
        ull r2 = __shfl_xor_sync(0xffffffffu, s2, 1);
        ull r3 = __shfl_xor_sync(0xffffffffu, s3, 1);

        ull pi0, pi1, pf0, pf1, pg0, pg1, po0, po1;
        if (!parity) {
            pi0 = acc[0][0]; pi1 = acc[1][0]; pf0 = acc[0][1]; pf1 = acc[1][1];
            pg0 = r0; pg1 = r1; po0 = r2; po1 = r3;
        } else {
            pg0 = acc[2][0]; pg1 = acc[3][0]; po0 = acc[2][1]; po1 = acc[3][1];
            pi0 = r0; pi1 = r1; pf0 = r2; pf1 = r3;
        }
        float iv[4], fv[4], gv[4], ov[4];
        upk2(pi0, iv[0], iv[1]); upk2(pi1, iv[2], iv[3]);
        upk2(pf0, fv[0], fv[1]); upk2(pf1, fv[2], fv[3]);
        upk2(pg0, gv[0], gv[1]); upk2(pg1, gv[2], gv[3]);
        upk2(po0, ov[0], ov[1]); upk2(po1, ov[2], ov[3]);

        float hn[4];
#pragma unroll
        for (int j = 0; j < 4; j++) {
            float gi = iv[j] + pg[j][0];
            float gf = fv[j] + pg[j][1];
            float gg = gv[j] + pg[j][2];
            float go = ov[j] + pg[j][3];
            float Cn = sigma(gf) * Creg[j] + sigma(gi) * tanha(gg);
            hn[j] = sigma(go) * tanha(Cn);
            Creg[j] = Cn;
            int b = bcell0 + j;
            size_t ob = ((size_t)b * LL + t) * HH + h;
            __stcs(&out_h[ob], hn[j]);
            __stcs(&out_c[ob], Cn);
        }
        // write h transposed [h][b]: 4 consecutive b -> one float4
        __stcg((float4*)&hnext[(size_t)h * BB + bcell0],
               make_float4(hn[0], hn[1], hn[2], hn[3]));

        // --- grid barrier ---
        if (t != LL - 1) {
            __threadfence();
            __syncthreads();
            if (tid == 0) {
                atomicAdd((unsigned*)&g_bar, 1u);
                unsigned tgt = 128u * (unsigned)(t + 1);
                while (g_bar < tgt) { __nanosleep(64); }
            }
            __syncthreads();
        }
    }
}

// ---------------- launch ----------------
extern "C" void kernel_launch(void* const* d_in, const int* in_sizes, int n_in,
                              void* d_out, int out_size) {
    const float* x   = (const float*)d_in[0];
    const float* Wih = (const float*)d_in[1];
    const float* bih = (const float*)d_in[2];
    const float* Wmx = (const float*)d_in[3];
    const float* bmx = (const float*)d_in[4];
    const float* Wmh = (const float*)d_in[5];
    const float* bmh = (const float*)d_in[6];
    const float* Whm = (const float*)d_in[7];
    const float* bhm = (const float*)d_in[8];
    const float* Wa  = (const float*)d_in[9];
    const float* ba  = (const float*)d_in[10];

    float* out    = (float*)d_out;
    float* out_h  = out;
    float* out_c  = out + (size_t)BB * LL * HH;
    float* out_xt = out + (size_t)2 * BB * LL * HH;

    float *preG2, *W2, *Wcomb, *biasc;
    cudaGetSymbolAddress((void**)&preG2, g_preG2);
    cudaGetSymbolAddress((void**)&W2, g_W2);
    cudaGetSymbolAddress((void**)&Wcomb, g_Wcomb);
    cudaGetSymbolAddress((void**)&biasc, g_biasc);

    // init state + barrier
    zero_init<<<(HH * BB + 255) / 256, 256>>>(HH * BB);

    // attention path (time-invariant softmax)
    attn_xtilde<<<BB, 256>>>(x, Wa, ba, out_xt);

    // combined bias row: bih + bhm + (bmx+bmh)@Whm
    bias_comb<<<G4H / 256, 256>>>(bih, bhm, bmx, bmh, Whm);

    // Wcomb = Wih + Wmx @ Whm      [256 x 2048]
    sgemm_f32<<<dim3(G4H / BN, CC / BM), 256>>>(
        Wmx, Whm, Wcomb, CC, G4H, HH, nullptr, Wih);

    // W2 = Wmh @ Whm               [512 x 2048]
    sgemm_f32<<<dim3(G4H / BN, HH / BM), 256>>>(
        Wmh, Whm, W2, HH, G4H, HH, nullptr, nullptr);
    interleaveW2<<<(HH * G4H) / 256, 256>>>();

    // preG2 = X @ Wcomb + biasc    [32768 x 2048]  (the ONLY big GEMM now)
    sgemm_f32<<<dim3(G4H / BN, (BB * LL) / BM), 256>>>(
        x, Wcomb, preG2, BB * LL, G4H, CC, biasc, nullptr);

    // persistent recurrence: 128 steps, W2 in SMEM, grid barrier between steps
    int smem_bytes = (HH * 64 + 2 * CHK * HSP) * sizeof(float);
    cudaFuncSetAttribute(lstm_persist, cudaFuncAttributeMaxDynamicSharedMemorySize, smem_bytes);
    lstm_persist<<<dim3(32, 4), 256, smem_bytes>>>(preG2, out_h, out_c);
}